// round 4
// baseline (speedup 1.0000x reference)
#include <cuda_runtime.h>
#include <cuda_bf16.h>
#include <math.h>
#include <stdint.h>

#define NB 32
#define NT 1000
#define ND 512
#define TT1 1001

// d_out layout: acoustic [32,1001,512] | token_num [32] | alphas_t [32,1001] | cif_peak [32,1001] | token_num2 [32]
#define N_AC   (NB*TT1*ND)
#define OFF_TN (N_AC)
#define OFF_AT (OFF_TN + NB)
#define OFF_CP (OFF_AT + NB*TT1)
#define OFF_TN2 (OFF_CP + NB*TT1)

// ---------------- scratch ----------------
__device__ __align__(1024) float g_y[NB*NT*ND];            // relu(conv) fp32
__device__ __align__(1024) __nv_bfloat16 g_A0[NB*NT*ND];   // enc bf16 splits
__device__ __align__(1024) __nv_bfloat16 g_A1[NB*NT*ND];
__device__ __align__(1024) __nv_bfloat16 g_A2[NB*NT*ND];
__device__ __align__(1024) __nv_bfloat16 g_B0[3*ND*ND];    // w splits, [tap][o][i]
__device__ __align__(1024) __nv_bfloat16 g_B1[3*ND*ND];
__device__ __align__(1024) __nv_bfloat16 g_B2[3*ND*ND];
__device__ float g_v[5*ND];
__device__ float g_c2;
__device__ float g_a2sum[NB*NT];
__device__ float g_coeff[NB*TT1];
__device__ int   g_firepos[NB*TT1];
__device__ int   g_ntok[NB];

// ---------------- helpers ----------------
__device__ __forceinline__ uint32_t smem_u32(const void* p) {
    uint32_t a;
    asm("{ .reg .u64 t; cvta.to.shared.u64 t, %1; cvt.u32.u64 %0, t; }" : "=r"(a) : "l"(p));
    return a;
}
__device__ __forceinline__ void cp16(uint32_t dst, const void* src, int srcsz) {
    asm volatile("cp.async.cg.shared.global [%0], [%1], 16, %2;" :: "r"(dst), "l"(src), "r"(srcsz) : "memory");
}
__device__ __forceinline__ void ldsm4(uint32_t* r, uint32_t addr) {
    asm volatile("ldmatrix.sync.aligned.m8n8.x4.shared.b16 {%0,%1,%2,%3}, [%4];"
        : "=r"(r[0]), "=r"(r[1]), "=r"(r[2]), "=r"(r[3]) : "r"(addr));
}
__device__ __forceinline__ void mma16816(float* d, const uint32_t* a, uint32_t b0, uint32_t b1) {
    asm volatile("mma.sync.aligned.m16n8k16.row.col.f32.bf16.bf16.f32 "
        "{%0,%1,%2,%3}, {%4,%5,%6,%7}, {%8,%9}, {%0,%1,%2,%3};"
        : "+f"(d[0]), "+f"(d[1]), "+f"(d[2]), "+f"(d[3])
        : "r"(a[0]), "r"(a[1]), "r"(a[2]), "r"(a[3]), "r"(b0), "r"(b1));
}
__device__ __forceinline__ float sigmoidf_acc(float x) {
    if (x >= 0.f) { float z = expf(-x); return 1.f / (1.f + z); }
    float z = expf(x); return z / (1.f + z);
}

// ---------------- prep: bf16 3-way splits ----------------
__global__ void k_split_enc(const float* __restrict__ enc) {
    int idx = blockIdx.x * blockDim.x + threadIdx.x;
    if (idx >= NB*NT*ND) return;
    float x = enc[idx];
    __nv_bfloat16 b0 = __float2bfloat16(x);
    float r1 = x - __bfloat162float(b0);
    __nv_bfloat16 b1 = __float2bfloat16(r1);
    __nv_bfloat16 b2 = __float2bfloat16(r1 - __bfloat162float(b1));
    g_A0[idx] = b0; g_A1[idx] = b1; g_A2[idx] = b2;
}

__global__ void k_split_w(const float* __restrict__ cw) {
    int idx = blockIdx.x * blockDim.x + threadIdx.x;
    if (idx >= 3*ND*ND) return;
    int tap = idx / (ND*ND);
    int rem = idx - tap*ND*ND;
    int o = rem >> 9, i = rem & 511;
    float x = cw[(o*ND + i)*3 + tap];
    __nv_bfloat16 b0 = __float2bfloat16(x);
    float r1 = x - __bfloat162float(b0);
    __nv_bfloat16 b1 = __float2bfloat16(r1);
    __nv_bfloat16 b2 = __float2bfloat16(r1 - __bfloat162float(b1));
    g_B0[idx] = b0; g_B1[idx] = b1; g_B2[idx] = b2;
}

__global__ void k_prep_v(const float* __restrict__ uw, const float* __restrict__ w2) {
    int i = blockIdx.x;
    int j = threadIdx.x >> 5, lane = threadIdx.x & 31;
    float s = 0.f;
    for (int o = lane; o < ND; o += 32) s += uw[((size_t)i*ND + o)*5 + j] * w2[o];
    #pragma unroll
    for (int o = 16; o > 0; o >>= 1) s += __shfl_xor_sync(0xffffffffu, s, o);
    if (lane == 0) g_v[j*ND + i] = s;
}

__global__ void k_prep_c2(const float* __restrict__ ub, const float* __restrict__ w2,
                          const float* __restrict__ b2) {
    int lane = threadIdx.x;
    float s = 0.f;
    for (int o = lane; o < ND; o += 32) s += ub[o] * w2[o];
    #pragma unroll
    for (int o = 16; o > 0; o >>= 1) s += __shfl_xor_sync(0xffffffffu, s, o);
    if (lane == 0) g_c2 = s + b2[0];
}

// ---------------- K1: mma.sync bf16x6 conv GEMM, 2-level accumulation ----------------
// CTA 128x128, 256 thr (8 warps): warp tile 64x32 (2 m-warps x 4 n-warps).
// phases: tap(3) x i-chunk(8 of 64). stage = {A0,A1,A2,B0,B1,B2} x [128 rows][64 bf16]
#define TILE_B   16384
#define STAGE_B  (6*TILE_B)
#define SMEM_TOTAL_TC (2*STAGE_B)

__global__ void __launch_bounds__(256) k_conv_tc(const float* __restrict__ cb) {
    extern __shared__ char dsm[];
    const uint32_t smem = smem_u32(dsm);
    const int tid  = threadIdx.x;
    const int wid  = tid >> 5, lane = tid & 31;
    const int o0   = blockIdx.x * 128;
    const int t0   = blockIdx.y * 128;
    const int b    = blockIdx.z;
    const int moff = (wid >> 2) * 64;    // 2 m-warps of 64
    const int noff = (wid & 3) * 32;     // 4 n-warps of 32

    float accm[4][4][4];                 // master
    #pragma unroll
    for (int f = 0; f < 4; ++f)
        #pragma unroll
        for (int g = 0; g < 4; ++g)
            #pragma unroll
            for (int q = 0; q < 4; ++q) accm[f][g][q] = 0.f;

    // loader: 1024 cp16 per tile, 256 threads -> 4 per tile; row = tid>>1, chunks 4*(tid&1)+0..3
    auto load_stage = [&](int ph, uint32_t stage) {
        const int tap = ph >> 3;
        const int i0  = (ph & 7) * 64;
        const int r   = tid >> 1;
        const int ch0 = (tid & 1) * 4;
        const uint32_t rb = (uint32_t)r * 128;
        const int t   = t0 + r + tap - 1;
        const int ok  = (t >= 0 && t < NT);
        const size_t aoff = ((size_t)(b*NT + (ok ? t : 0)))*ND + i0;
        const size_t woff = ((size_t)tap*ND + (o0 + r))*ND + i0;
        const int sz = ok ? 16 : 0;
        #pragma unroll
        for (int cc = 0; cc < 4; ++cc) {
            int c = ch0 + cc;
            uint32_t sw = rb + (uint32_t)((c ^ (r & 7)) << 4);
            cp16(stage + 0*TILE_B + sw, g_A0 + aoff + c*8, sz);
            cp16(stage + 1*TILE_B + sw, g_A1 + aoff + c*8, sz);
            cp16(stage + 2*TILE_B + sw, g_A2 + aoff + c*8, sz);
            cp16(stage + 3*TILE_B + sw, g_B0 + woff + c*8, 16);
            cp16(stage + 4*TILE_B + sw, g_B1 + woff + c*8, 16);
            cp16(stage + 5*TILE_B + sw, g_B2 + woff + c*8, 16);
        }
        asm volatile("cp.async.commit_group;" ::: "memory");
    };

    load_stage(0, smem);

    const int arow_lo = (lane & 15);
    const int acol_hi = (lane >> 4);
    const int brow_lo = (lane & 7) + ((lane >> 4) << 3);
    const int bcol_hi = ((lane >> 3) & 1);

    for (int ph = 0; ph < 24; ++ph) {
        const uint32_t stage = smem + (uint32_t)(ph & 1) * STAGE_B;
        if (ph < 23) load_stage(ph + 1, smem + (uint32_t)((ph + 1) & 1) * STAGE_B);
        if (ph < 23) asm volatile("cp.async.wait_group 1;" ::: "memory");
        else         asm volatile("cp.async.wait_group 0;" ::: "memory");
        __syncthreads();

        float accp[4][4][4];             // phase accumulator (zeroed)
        #pragma unroll
        for (int f = 0; f < 4; ++f)
            #pragma unroll
            for (int g = 0; g < 4; ++g)
                #pragma unroll
                for (int q = 0; q < 4; ++q) accp[f][g][q] = 0.f;

        #pragma unroll
        for (int ks = 0; ks < 4; ++ks) {
            // hoist all B-split fragments for this kstep (n32 -> 2 ldsm4 per split)
            uint32_t bfr[3][2][4];
            #pragma unroll
            for (int bs = 0; bs < 3; ++bs) {
                #pragma unroll
                for (int g4 = 0; g4 < 2; ++g4) {
                    int row = noff + 16*g4 + brow_lo;
                    int c   = ks*2 + bcol_hi;
                    ldsm4(bfr[bs][g4], stage + (uint32_t)(3+bs)*TILE_B
                          + (uint32_t)row*128 + (uint32_t)((c ^ (row & 7)) << 4));
                }
            }
            // A-splits in order small->large: A1 {B0,B1}, A2 {B0}, A0 {B1,B2,B0}
            #pragma unroll
            for (int ai = 0; ai < 3; ++ai) {
                const int as   = (ai == 0) ? 1 : (ai == 1) ? 2 : 0;
                uint32_t afr[4][4];
                #pragma unroll
                for (int f = 0; f < 4; ++f) {
                    int row = moff + 16*f + arow_lo;
                    int c   = ks*2 + acol_hi;
                    ldsm4(afr[f], stage + (uint32_t)as*TILE_B
                          + (uint32_t)row*128 + (uint32_t)((c ^ (row & 7)) << 4));
                }
                #pragma unroll
                for (int bi = 0; bi < 3; ++bi) {
                    int bs;
                    if (as == 1)      { if (bi >= 2) continue; bs = bi; }          // B0,B1
                    else if (as == 2) { if (bi >= 1) continue; bs = 0; }           // B0
                    else              { bs = (bi == 0) ? 1 : (bi == 1) ? 2 : 0; }  // B1,B2,B0
                    #pragma unroll
                    for (int f = 0; f < 4; ++f) {
                        #pragma unroll
                        for (int g4 = 0; g4 < 2; ++g4) {
                            mma16816(accp[f][2*g4],   afr[f], bfr[bs][g4][0], bfr[bs][g4][1]);
                            mma16816(accp[f][2*g4+1], afr[f], bfr[bs][g4][2], bfr[bs][g4][3]);
                        }
                    }
                }
            }
        }
        // merge phase sum into master (one fp32 add per element per phase)
        #pragma unroll
        for (int f = 0; f < 4; ++f)
            #pragma unroll
            for (int g = 0; g < 4; ++g)
                #pragma unroll
                for (int q = 0; q < 4; ++q) accm[f][g][q] += accp[f][g][q];
        __syncthreads();
    }

    // epilogue: bias + relu -> g_y
    #pragma unroll
    for (int f = 0; f < 4; ++f) {
        int r0 = t0 + moff + 16*f + (lane >> 2);
        #pragma unroll
        for (int g = 0; g < 4; ++g) {
            int og = o0 + noff + 8*g + 2*(lane & 3);
            float b0v = cb[og], b1v = cb[og + 1];
            if (r0 < NT) {
                float2 o2;
                o2.x = fmaxf(accm[f][g][0] + b0v, 0.f);
                o2.y = fmaxf(accm[f][g][1] + b1v, 0.f);
                *(float2*)(g_y + ((size_t)(b*NT + r0))*ND + og) = o2;
            }
            if (r0 + 8 < NT) {
                float2 o2;
                o2.x = fmaxf(accm[f][g][2] + b0v, 0.f);
                o2.y = fmaxf(accm[f][g][3] + b1v, 0.f);
                *(float2*)(g_y + ((size_t)(b*NT + r0 + 8))*ND + og) = o2;
            }
        }
    }
}

// ---------------- K2: projections -> alphas_t[t<T], a2sum ----------------
__global__ void __launch_bounds__(256) k_proj(const float* __restrict__ mask,
        const float* __restrict__ w1, const float* __restrict__ b1,
        float* __restrict__ out_at) {
    int warp = threadIdx.x >> 5, lane = threadIdx.x & 31;
    int m = blockIdx.x * 8 + warp;
    if (m >= NB*NT) return;
    int b = m / NT, t = m - b*NT;
    const float4* yr  = (const float4*)(g_y + (size_t)m*ND);
    const float4* w1r = (const float4*)w1;
    float s[6] = {0.f,0.f,0.f,0.f,0.f,0.f};
    #pragma unroll
    for (int r = 0; r < 4; ++r) {
        int i4 = lane + 32*r;
        float4 h = yr[i4];
        float4 w = w1r[i4];
        s[0] += h.x*w.x + h.y*w.y + h.z*w.z + h.w*w.w;
        #pragma unroll
        for (int j = 0; j < 5; ++j) {
            float4 vv = *(const float4*)(g_v + j*ND + i4*4);
            s[1+j] += h.x*vv.x + h.y*vv.y + h.z*vv.z + h.w*vv.w;
        }
    }
    #pragma unroll
    for (int q = 0; q < 6; ++q)
        #pragma unroll
        for (int o = 16; o > 0; o >>= 1)
            s[q] += __shfl_xor_sync(0xffffffffu, s[q], o);
    if (lane == 0) {
        float mv = mask[b*NT + t];
        float alpha = fmaxf(sigmoidf_acc(s[0] + b1[0]), 0.f) * mv;
        float m2 = (t == 0) ? 1.f : mask[b*NT + t - 1];
        out_at[b*TT1 + t] = alpha + (m2 - mv) * 0.45f;
        float c2 = g_c2;
        float s2 = 0.f;
        #pragma unroll
        for (int j = 0; j < 5; ++j) s2 += fmaxf(sigmoidf_acc(s[1+j] + c2), 0.f);
        g_a2sum[m] = s2 * mv;
    }
}

// ---------------- K3: scalar CIF scan per batch ----------------
__global__ void k_scan(const float* __restrict__ mask, float* __restrict__ out) {
    int b = blockIdx.x, lane = threadIdx.x;
    float* out_at = out + OFF_AT;
    float* out_cp = out + OFF_CP;

    double s2 = 0.0;
    for (int t = lane; t < NT; t += 32) s2 += (double)g_a2sum[b*NT + t];
    #pragma unroll
    for (int o = 16; o > 0; o >>= 1) s2 += __shfl_xor_sync(0xffffffffu, s2, o);
    if (lane == 0) out[OFF_TN2 + b] = (float)s2;

    float tailv = mask[b*NT + NT - 1] * 0.45f;
    if (lane == 0) out_at[b*TT1 + NT] = tailv;

    float integ = 0.f; double asum = 0.0; int ntok = 0;
    for (int c = 0; c < TT1; c += 32) {
        int t = c + lane;
        float av = 0.f;
        if (t < NT) av = out_at[b*TT1 + t];
        else if (t == NT) av = tailv;
        float my_peak = 0.f, my_coeff = 0.f;
        int lim = TT1 - c; if (lim > 32) lim = 32;
        for (int s = 0; s < lim; ++s) {
            float alpha = __shfl_sync(0xffffffffu, av, s);
            asum += (double)alpha;
            float dist = 1.f - integ;
            integ += alpha;
            float fires = integ;
            float cur = alpha;
            if (fires >= 1.f) {
                integ -= 1.f;
                cur = dist;
                if (lane == 0) g_firepos[b*TT1 + ntok] = c + s;
                ntok++;
            }
            if (lane == s) { my_peak = fires; my_coeff = cur; }
        }
        if (t < TT1) { out_cp[b*TT1 + t] = my_peak; g_coeff[b*TT1 + t] = my_coeff; }
    }
    if (lane == 0) { out[OFF_TN + b] = floorf((float)asum); g_ntok[b] = ntok; }
}

// ---------------- K4: parallel token gather-sum ----------------
__global__ void __launch_bounds__(128) k_gather(const float* __restrict__ enc,
                                                float* __restrict__ out) {
    int b = blockIdx.y, n = blockIdx.x, tid = threadIdx.x;
    const float* at = out + OFF_AT;
    float4 acc = make_float4(0.f,0.f,0.f,0.f);
    if (n < g_ntok[b]) {
        int te = g_firepos[b*TT1 + n];
        int tstart = 0;
        if (n > 0) {
            int tp = g_firepos[b*TT1 + n - 1];
            float lw = at[b*TT1 + tp] - g_coeff[b*TT1 + tp];
            if (tp < NT) {
                float4 h = *(const float4*)(enc + ((size_t)b*NT + tp)*ND + tid*4);
                acc.x = lw*h.x; acc.y = lw*h.y; acc.z = lw*h.z; acc.w = lw*h.w;
            }
            tstart = tp + 1;
        }
        for (int t = tstart; t <= te; ++t) {
            if (t >= NT) break;
            float cf = g_coeff[b*TT1 + t];
            float4 h = *(const float4*)(enc + ((size_t)b*NT + t)*ND + tid*4);
            acc.x = fmaf(cf, h.x, acc.x);
            acc.y = fmaf(cf, h.y, acc.y);
            acc.z = fmaf(cf, h.z, acc.z);
            acc.w = fmaf(cf, h.w, acc.w);
        }
    }
    *(float4*)(out + ((size_t)(b*TT1 + n))*ND + tid*4) = acc;
}

// ---------------- launch ----------------
extern "C" void kernel_launch(void* const* d_in, const int* in_sizes, int n_in,
                              void* d_out, int out_size) {
    (void)in_sizes; (void)n_in; (void)out_size;
    const float* enc  = (const float*)d_in[0];
    const float* mask = (const float*)d_in[1];
    const float* cw   = (const float*)d_in[2];
    const float* cb   = (const float*)d_in[3];
    const float* uw   = (const float*)d_in[4];
    const float* ub   = (const float*)d_in[5];
    const float* w1   = (const float*)d_in[6];
    const float* b1   = (const float*)d_in[7];
    const float* w2   = (const float*)d_in[8];
    const float* b2   = (const float*)d_in[9];
    float* out = (float*)d_out;

    cudaFuncSetAttribute(k_conv_tc, cudaFuncAttributeMaxDynamicSharedMemorySize, SMEM_TOTAL_TC);

    k_split_enc<<<(NB*NT*ND + 255)/256, 256>>>(enc);
    k_split_w<<<(3*ND*ND + 255)/256, 256>>>(cw);
    k_prep_v<<<ND, 160>>>(uw, w2);
    k_prep_c2<<<1, 32>>>(ub, w2, b2);

    dim3 g1(4, 8, NB);   // o-tiles x t-tiles x batch
    k_conv_tc<<<g1, 256, SMEM_TOTAL_TC>>>(cb);

    k_proj<<<(NB*NT)/8, 256>>>(mask, w1, b1, out + OFF_AT);
    k_scan<<<NB, 32>>>(mask, out);

    dim3 g4(TT1, NB);
    k_gather<<<g4, 128>>>(enc, out);
}

// round 5
// speedup vs baseline: 1.4437x; 1.4437x over previous
#include <cuda_runtime.h>
#include <math.h>
#include <stdint.h>

typedef unsigned long long ull;

#define NB 32
#define NT 1000
#define ND 512
#define TT1 1001

// d_out layout: acoustic [32,1001,512] | token_num [32] | alphas_t [32,1001] | cif_peak [32,1001] | token_num2 [32]
#define N_AC   (NB*TT1*ND)
#define OFF_TN (N_AC)
#define OFF_AT (OFF_TN + NB)
#define OFF_CP (OFF_AT + NB*TT1)
#define OFF_TN2 (OFF_CP + NB*TT1)

// ---------------- scratch ----------------
__device__ __align__(1024) float g_y[NB*NT*ND];   // relu(conv) output
__device__ __align__(1024) float g_Wt[3*ND*ND];   // conv weights [k][i][o]
__device__ float g_v[5*ND];
__device__ float g_c2;
__device__ float g_a2sum[NB*NT];
__device__ float g_coeff[NB*TT1];
__device__ int   g_firepos[NB*TT1];
__device__ int   g_ntok[NB];

__device__ __forceinline__ void ffma2(ull &d, ull a, ull b) {
    asm("fma.rn.f32x2 %0, %1, %2, %0;" : "+l"(d) : "l"(a), "l"(b));
}
__device__ __forceinline__ uint32_t smem_u32(const void* p) {
    uint32_t a;
    asm("{ .reg .u64 t; cvta.to.shared.u64 t, %1; cvt.u32.u64 %0, t; }" : "=r"(a) : "l"(p));
    return a;
}
__device__ __forceinline__ void cp16(uint32_t dst, const void* src) {
    asm volatile("cp.async.cg.shared.global [%0], [%1], 16;" :: "r"(dst), "l"(src) : "memory");
}
__device__ __forceinline__ float sigmoidf_acc(float x) {
    if (x >= 0.f) { float z = expf(-x); return 1.f / (1.f + z); }
    float z = expf(x); return z / (1.f + z);
}

// ---------------- prep kernels ----------------
__global__ void k_prep_wt(const float* __restrict__ cw) {
    int idx = blockIdx.x * blockDim.x + threadIdx.x;
    if (idx < 3*ND*ND) {
        int o = idx & 511;
        int i = (idx >> 9) & 511;
        int k = idx >> 18;
        g_Wt[idx] = cw[(o*ND + i)*3 + k];
    }
}

__global__ void k_prep_v(const float* __restrict__ uw, const float* __restrict__ w2) {
    int i = blockIdx.x;
    int j = threadIdx.x >> 5, lane = threadIdx.x & 31;
    float s = 0.f;
    for (int o = lane; o < ND; o += 32) s += uw[((size_t)i*ND + o)*5 + j] * w2[o];
    #pragma unroll
    for (int o = 16; o > 0; o >>= 1) s += __shfl_xor_sync(0xffffffffu, s, o);
    if (lane == 0) g_v[j*ND + i] = s;
}

__global__ void k_prep_c2(const float* __restrict__ ub, const float* __restrict__ w2,
                          const float* __restrict__ b2) {
    __shared__ float red[4];
    int tid = threadIdx.x, lane = tid & 31, wid = tid >> 5;
    float s = 0.f;
    for (int o = tid; o < ND; o += 128) s += ub[o] * w2[o];
    #pragma unroll
    for (int o = 16; o > 0; o >>= 1) s += __shfl_xor_sync(0xffffffffu, s, o);
    if (lane == 0) red[wid] = s;
    __syncthreads();
    if (tid == 0) g_c2 = red[0] + red[1] + red[2] + red[3] + b2[0];
}

// ---------------- K1: double-buffered FFMA2 conv GEMM ----------------
// C[t,o] = relu( sum_{k,i} enc[b, t+k-1, i] * Wt[k][i][o] + conv_b[o] )
// CTA: 256 thr, tile 128t x 128o, BK=16, 32 chunks, 2-stage pipeline.
// stage layout: As2 [16][132] float2 (dup pairs, row r -> t=t0-1+r) 16896B,
//               Bs  [3][16][128] float 24576B  -> 41472B/stage.
#define A_BYTES 16896
#define STAGE_BYTES 41472
#define SMEM_CONV (2*STAGE_BYTES)

__global__ void __launch_bounds__(256, 2) k_conv_gemm(const float* __restrict__ enc,
                                                      const float* __restrict__ cb) {
    extern __shared__ __align__(16) char dsm[];
    float2* As2base = (float2*)dsm;                 // per stage: [16][132] float2
    const int b  = blockIdx.z;
    const int t0 = blockIdx.x * 128;
    const int o0 = blockIdx.y * 128;
    const int tid = threadIdx.x;
    const int tx = tid & 15;     // o direction
    const int ty = tid >> 4;     // t direction

    const uint32_t smem = smem_u32(dsm);

    ull acc[8][4];
    #pragma unroll
    for (int m = 0; m < 8; ++m)
        #pragma unroll
        for (int n = 0; n < 4; ++n) acc[m][n] = 0ull;

    // ---- A LDG: chunk i0, 520 float4 (r=idx>>2 in 0..129 -> t=t0-1+r, c4=idx&3) ----
    auto ldgA = [&](int i0, float4* vbuf) {
        #pragma unroll
        for (int p = 0; p < 3; ++p) {
            int idx = tid + p*256;
            vbuf[p] = make_float4(0.f, 0.f, 0.f, 0.f);
            if (idx < 520) {
                int r = idx >> 2, c4 = idx & 3;
                int t = t0 - 1 + r;
                if (t >= 0 && t < NT)
                    vbuf[p] = *(const float4*)(enc + ((size_t)b*NT + t)*ND + i0 + c4*4);
            }
        }
    };
    // ---- A STS: duplicate into As2 of stage s ----
    auto stsA = [&](int s, const float4* vbuf) {
        float2* As2 = (float2*)(dsm + s*STAGE_BYTES);
        #pragma unroll
        for (int p = 0; p < 3; ++p) {
            int idx = tid + p*256;
            if (idx < 520) {
                int r = idx >> 2, c4 = idx & 3;
                float4 val = vbuf[p];
                As2[(c4*4+0)*132 + r] = make_float2(val.x, val.x);
                As2[(c4*4+1)*132 + r] = make_float2(val.y, val.y);
                As2[(c4*4+2)*132 + r] = make_float2(val.z, val.z);
                As2[(c4*4+3)*132 + r] = make_float2(val.w, val.w);
            }
        }
    };
    // ---- B cp.async: chunk i0 into stage s ----
    auto cpB = [&](int s, int i0) {
        uint32_t Bs = smem + s*STAGE_BYTES + A_BYTES;
        #pragma unroll
        for (int p = 0; p < 6; ++p) {
            int idx = tid + p*256;            // < 1536
            int kk = idx >> 9;
            int ii = (idx >> 5) & 15;
            int c4 = idx & 31;
            cp16(Bs + (uint32_t)(((kk*16 + ii)*128 + c4*4)*4),
                 g_Wt + ((size_t)kk*ND + i0 + ii)*ND + o0 + c4*4);
        }
        asm volatile("cp.async.commit_group;" ::: "memory");
    };

    // ---- prologue: fill both stages (chunks 0,1) ----
    float4 vbuf[3];
    ldgA(0, vbuf);  stsA(0, vbuf);  cpB(0, 0);
    ldgA(16, vbuf); stsA(1, vbuf);  cpB(1, 16);

    for (int c = 0; c < 32; ++c) {
        const int s = c & 1;
        if (c < 30) asm volatile("cp.async.wait_group 1;" ::: "memory");
        else        asm volatile("cp.async.wait_group 0;" ::: "memory");
        __syncthreads();   // B(c) landed (wait_group) + A(c) STS visible + stage free

        if (c < 30) ldgA((c + 2) * 16, vbuf);   // prefetch next-next A into regs

        // ---- compute chunk c from stage s (identical math/order to R1) ----
        const float2* As2 = (const float2*)(dsm + s*STAGE_BYTES);
        const uint32_t BsU = smem + s*STAGE_BYTES + A_BYTES;
        const float* Bsf = (const float*)(dsm + s*STAGE_BYTES + A_BYTES);
        (void)BsU;
        #pragma unroll
        for (int ii = 0; ii < 16; ++ii) {
            ull a[10];
            const ulonglong2* ap = (const ulonglong2*)(As2 + ii*132 + ty*8);
            ulonglong2 q;
            q = ap[0]; a[0] = q.x; a[1] = q.y;
            q = ap[1]; a[2] = q.x; a[3] = q.y;
            q = ap[2]; a[4] = q.x; a[5] = q.y;
            q = ap[3]; a[6] = q.x; a[7] = q.y;
            q = ap[4]; a[8] = q.x; a[9] = q.y;
            #pragma unroll
            for (int k = 0; k < 3; ++k) {
                const ulonglong2* bp = (const ulonglong2*)(Bsf + (k*16 + ii)*128 + tx*8);
                ulonglong2 b01 = bp[0];
                ulonglong2 b23 = bp[1];
                #pragma unroll
                for (int m = 0; m < 8; ++m) {
                    ffma2(acc[m][0], a[m+k], b01.x);
                    ffma2(acc[m][1], a[m+k], b01.y);
                    ffma2(acc[m][2], a[m+k], b23.x);
                    ffma2(acc[m][3], a[m+k], b23.y);
                }
            }
        }
        __syncthreads();   // compute on stage s done -> safe to refill

        if (c < 30) { stsA(s, vbuf); cpB(s, (c + 2) * 16); }
    }

    // ---- epilogue: +bias, relu, store to g_y ----
    float bias[8];
    #pragma unroll
    for (int j = 0; j < 8; ++j) bias[j] = cb[o0 + tx*8 + j];
    #pragma unroll
    for (int m = 0; m < 8; ++m) {
        int t = t0 + ty*8 + m;
        if (t < NT) {
            float outv[8];
            #pragma unroll
            for (int n = 0; n < 4; ++n) {
                float lo = __uint_as_float((unsigned)(acc[m][n] & 0xffffffffull));
                float hi = __uint_as_float((unsigned)(acc[m][n] >> 32));
                outv[2*n]   = fmaxf(lo + bias[2*n],   0.f);
                outv[2*n+1] = fmaxf(hi + bias[2*n+1], 0.f);
            }
            float4* yp = (float4*)(g_y + ((size_t)b*NT + t)*ND + o0 + tx*8);
            yp[0] = make_float4(outv[0], outv[1], outv[2], outv[3]);
            yp[1] = make_float4(outv[4], outv[5], outv[6], outv[7]);
        }
    }
}

// ---------------- K2: projections -> alphas_t[t<T], a2sum ----------------
__global__ void __launch_bounds__(256) k_proj(const float* __restrict__ mask,
        const float* __restrict__ w1, const float* __restrict__ b1,
        float* __restrict__ out_at) {
    int warp = threadIdx.x >> 5, lane = threadIdx.x & 31;
    int m = blockIdx.x * 8 + warp;
    if (m >= NB*NT) return;
    int b = m / NT, t = m - b*NT;
    const float4* yr  = (const float4*)(g_y + (size_t)m*ND);
    const float4* w1r = (const float4*)w1;
    float s[6] = {0.f,0.f,0.f,0.f,0.f,0.f};
    #pragma unroll
    for (int r = 0; r < 4; ++r) {
        int i4 = lane + 32*r;
        float4 h = yr[i4];
        float4 w = w1r[i4];
        s[0] += h.x*w.x + h.y*w.y + h.z*w.z + h.w*w.w;
        #pragma unroll
        for (int j = 0; j < 5; ++j) {
            float4 vv = *(const float4*)(g_v + j*ND + i4*4);
            s[1+j] += h.x*vv.x + h.y*vv.y + h.z*vv.z + h.w*vv.w;
        }
    }
    #pragma unroll
    for (int q = 0; q < 6; ++q)
        #pragma unroll
        for (int o = 16; o > 0; o >>= 1)
            s[q] += __shfl_xor_sync(0xffffffffu, s[q], o);
    if (lane == 0) {
        float mv = mask[b*NT + t];
        float alpha = fmaxf(sigmoidf_acc(s[0] + b1[0]), 0.f) * mv;
        float m2 = (t == 0) ? 1.f : mask[b*NT + t - 1];
        out_at[b*TT1 + t] = alpha + (m2 - mv) * 0.45f;
        float c2 = g_c2;
        float s2 = 0.f;
        #pragma unroll
        for (int j = 0; j < 5; ++j) s2 += fmaxf(sigmoidf_acc(s[1+j] + c2), 0.f);
        g_a2sum[m] = s2 * mv;
    }
}

// ---------------- K3: scalar CIF scan per batch ----------------
__global__ void k_scan(const float* __restrict__ mask, float* __restrict__ out) {
    int b = blockIdx.x, lane = threadIdx.x;
    float* out_at = out + OFF_AT;
    float* out_cp = out + OFF_CP;

    double s2 = 0.0;
    for (int t = lane; t < NT; t += 32) s2 += (double)g_a2sum[b*NT + t];
    #pragma unroll
    for (int o = 16; o > 0; o >>= 1) s2 += __shfl_xor_sync(0xffffffffu, s2, o);
    if (lane == 0) out[OFF_TN2 + b] = (float)s2;

    float tailv = mask[b*NT + NT - 1] * 0.45f;
    if (lane == 0) out_at[b*TT1 + NT] = tailv;

    float integ = 0.f; double asum = 0.0; int ntok = 0;
    for (int c = 0; c < TT1; c += 32) {
        int t = c + lane;
        float av = 0.f;
        if (t < NT) av = out_at[b*TT1 + t];
        else if (t == NT) av = tailv;
        float my_peak = 0.f, my_coeff = 0.f;
        int lim = TT1 - c; if (lim > 32) lim = 32;
        for (int s = 0; s < lim; ++s) {
            float alpha = __shfl_sync(0xffffffffu, av, s);
            asum += (double)alpha;
            float dist = 1.f - integ;
            integ += alpha;
            float fires = integ;
            float cur = alpha;
            if (fires >= 1.f) {
                integ -= 1.f;
                cur = dist;
                if (lane == 0) g_firepos[b*TT1 + ntok] = c + s;
                ntok++;
            }
            if (lane == s) { my_peak = fires; my_coeff = cur; }
        }
        if (t < TT1) { out_cp[b*TT1 + t] = my_peak; g_coeff[b*TT1 + t] = my_coeff; }
    }
    if (lane == 0) { out[OFF_TN + b] = floorf((float)asum); g_ntok[b] = ntok; }
}

// ---------------- K4: parallel token gather-sum ----------------
__global__ void __launch_bounds__(128) k_gather(const float* __restrict__ enc,
                                                float* __restrict__ out) {
    int b = blockIdx.y, n = blockIdx.x, tid = threadIdx.x;
    const float* at = out + OFF_AT;
    float4 acc = make_float4(0.f,0.f,0.f,0.f);
    if (n < g_ntok[b]) {
        int te = g_firepos[b*TT1 + n];
        int tstart = 0;
        if (n > 0) {
            int tp = g_firepos[b*TT1 + n - 1];
            float lw = at[b*TT1 + tp] - g_coeff[b*TT1 + tp];
            if (tp < NT) {
                float4 h = *(const float4*)(enc + ((size_t)b*NT + tp)*ND + tid*4);
                acc.x = lw*h.x; acc.y = lw*h.y; acc.z = lw*h.z; acc.w = lw*h.w;
            }
            tstart = tp + 1;
        }
        for (int t = tstart; t <= te; ++t) {
            if (t >= NT) break;
            float cf = g_coeff[b*TT1 + t];
            float4 h = *(const float4*)(enc + ((size_t)b*NT + t)*ND + tid*4);
            acc.x = fmaf(cf, h.x, acc.x);
            acc.y = fmaf(cf, h.y, acc.y);
            acc.z = fmaf(cf, h.z, acc.z);
            acc.w = fmaf(cf, h.w, acc.w);
        }
    }
    *(float4*)(out + ((size_t)(b*TT1 + n))*ND + tid*4) = acc;
}

// ---------------- launch ----------------
extern "C" void kernel_launch(void* const* d_in, const int* in_sizes, int n_in,
                              void* d_out, int out_size) {
    (void)in_sizes; (void)n_in; (void)out_size;
    const float* enc  = (const float*)d_in[0];
    const float* mask = (const float*)d_in[1];
    const float* cw   = (const float*)d_in[2];
    const float* cb   = (const float*)d_in[3];
    const float* uw   = (const float*)d_in[4];
    const float* ub   = (const float*)d_in[5];
    const float* w1   = (const float*)d_in[6];
    const float* b1   = (const float*)d_in[7];
    const float* w2   = (const float*)d_in[8];
    const float* b2   = (const float*)d_in[9];
    float* out = (float*)d_out;

    cudaFuncSetAttribute(k_conv_gemm, cudaFuncAttributeMaxDynamicSharedMemorySize, SMEM_CONV);

    k_prep_wt<<<(3*ND*ND + 255)/256, 256>>>(cw);
    k_prep_v<<<ND, 160>>>(uw, w2);
    k_prep_c2<<<1, 128>>>(ub, w2, b2);

    dim3 g1(8, 4, NB);               // t-tiles x o-tiles x batch
    k_conv_gemm<<<g1, 256, SMEM_CONV>>>(enc, cb);

    k_proj<<<(NB*NT)/8, 256>>>(mask, w1, b1, out + OFF_AT);
    k_scan<<<NB, 32>>>(mask, out);

    dim3 g4(TT1, NB);
    k_gather<<<g4, 128>>>(enc, out);
}

// round 6
// speedup vs baseline: 1.6454x; 1.1397x over previous
#include <cuda_runtime.h>
#include <math.h>
#include <stdint.h>

typedef unsigned long long ull;

#define NB 32
#define NT 1000
#define ND 512
#define TT1 1001

// d_out layout: acoustic [32,1001,512] | token_num [32] | alphas_t [32,1001] | cif_peak [32,1001] | token_num2 [32]
#define N_AC   (NB*TT1*ND)
#define OFF_TN (N_AC)
#define OFF_AT (OFF_TN + NB)
#define OFF_CP (OFF_AT + NB*TT1)
#define OFF_TN2 (OFF_CP + NB*TT1)

// ---------------- scratch ----------------
__device__ __align__(1024) float g_y[NB*NT*ND];   // relu(conv) output
__device__ __align__(1024) float g_Wt[3*ND*ND];   // conv weights [k][i][o]
__device__ float g_v[5*ND];
__device__ float g_c2;
__device__ float g_a2sum[NB*NT];
__device__ float g_coeff[NB*TT1];
__device__ int   g_firepos[NB*TT1];
__device__ int   g_ntok[NB];

__device__ __forceinline__ void ffma2(ull &d, ull a, ull b) {
    asm("fma.rn.f32x2 %0, %1, %2, %0;" : "+l"(d) : "l"(a), "l"(b));
}
__device__ __forceinline__ ull dupf(float v) {
    ull d;
    asm("mov.b64 %0, {%1, %1};" : "=l"(d) : "f"(v));
    return d;
}
__device__ __forceinline__ uint32_t smem_u32(const void* p) {
    uint32_t a;
    asm("{ .reg .u64 t; cvta.to.shared.u64 t, %1; cvt.u32.u64 %0, t; }" : "=r"(a) : "l"(p));
    return a;
}
__device__ __forceinline__ void cp16(uint32_t dst, const void* src) {
    asm volatile("cp.async.cg.shared.global [%0], [%1], 16;" :: "r"(dst), "l"(src) : "memory");
}
__device__ __forceinline__ float sigmoidf_acc(float x) {
    if (x >= 0.f) { float z = expf(-x); return 1.f / (1.f + z); }
    float z = expf(x); return z / (1.f + z);
}

// ---------------- prep kernels ----------------
__global__ void k_prep_wt(const float* __restrict__ cw) {
    int idx = blockIdx.x * blockDim.x + threadIdx.x;
    if (idx < 3*ND*ND) {
        int o = idx & 511;
        int i = (idx >> 9) & 511;
        int k = idx >> 18;
        g_Wt[idx] = cw[(o*ND + i)*3 + k];
    }
}

__global__ void k_prep_v(const float* __restrict__ uw, const float* __restrict__ w2) {
    int i = blockIdx.x;
    int j = threadIdx.x >> 5, lane = threadIdx.x & 31;
    float s = 0.f;
    for (int o = lane; o < ND; o += 32) s += uw[((size_t)i*ND + o)*5 + j] * w2[o];
    #pragma unroll
    for (int o = 16; o > 0; o >>= 1) s += __shfl_xor_sync(0xffffffffu, s, o);
    if (lane == 0) g_v[j*ND + i] = s;
}

__global__ void k_prep_c2(const float* __restrict__ ub, const float* __restrict__ w2,
                          const float* __restrict__ b2) {
    __shared__ float red[4];
    int tid = threadIdx.x, lane = tid & 31, wid = tid >> 5;
    float s = 0.f;
    for (int o = tid; o < ND; o += 128) s += ub[o] * w2[o];
    #pragma unroll
    for (int o = 16; o > 0; o >>= 1) s += __shfl_xor_sync(0xffffffffu, s, o);
    if (lane == 0) red[wid] = s;
    __syncthreads();
    if (tid == 0) g_c2 = red[0] + red[1] + red[2] + red[3] + b2[0];
}

// ---------------- K1: double-buffered FFMA2 conv GEMM, packed-A smem ----------------
// C[t,o] = relu( sum_{k,i} enc[b, t+k-1, i] * Wt[k][i][o] + conv_b[o] )
// CTA: 256 thr, tile 128t x 128o, BK=16, 32 chunks, 2-stage pipeline.
// stage layout: Asp [16][132] float PACKED (row r -> t=t0-1+r) 8448B,
//               Bs  [3][16][128] float 24576B  -> 33024B/stage.
#define A_BYTES 8448
#define STAGE_BYTES 33024
#define SMEM_CONV (2*STAGE_BYTES)

__global__ void __launch_bounds__(256, 2) k_conv_gemm(const float* __restrict__ enc,
                                                      const float* __restrict__ cb) {
    extern __shared__ __align__(16) char dsm[];
    const int b  = blockIdx.z;
    const int t0 = blockIdx.x * 128;
    const int o0 = blockIdx.y * 128;
    const int tid = threadIdx.x;
    const int tx = tid & 15;     // o direction
    const int ty = tid >> 4;     // t direction

    const uint32_t smem = smem_u32(dsm);

    ull acc[8][4];
    #pragma unroll
    for (int m = 0; m < 8; ++m)
        #pragma unroll
        for (int n = 0; n < 4; ++n) acc[m][n] = 0ull;

    // ---- A LDG: chunk i0, 520 float4 (r=idx>>2 in 0..129 -> t=t0-1+r, c4=idx&3) ----
    auto ldgA = [&](int i0, float4* vbuf) {
        #pragma unroll
        for (int p = 0; p < 3; ++p) {
            int idx = tid + p*256;
            vbuf[p] = make_float4(0.f, 0.f, 0.f, 0.f);
            if (idx < 520) {
                int r = idx >> 2, c4 = idx & 3;
                int t = t0 - 1 + r;
                if (t >= 0 && t < NT)
                    vbuf[p] = *(const float4*)(enc + ((size_t)b*NT + t)*ND + i0 + c4*4);
            }
        }
    };
    // ---- A STS: packed floats into Asp[i][r] of stage s ----
    auto stsA = [&](int s, const float4* vbuf) {
        float* Asp = (float*)(dsm + s*STAGE_BYTES);
        #pragma unroll
        for (int p = 0; p < 3; ++p) {
            int idx = tid + p*256;
            if (idx < 520) {
                int r = idx >> 2, c4 = idx & 3;
                float4 val = vbuf[p];
                Asp[(c4*4+0)*132 + r] = val.x;
                Asp[(c4*4+1)*132 + r] = val.y;
                Asp[(c4*4+2)*132 + r] = val.z;
                Asp[(c4*4+3)*132 + r] = val.w;
            }
        }
    };
    // ---- B cp.async: chunk i0 into stage s ----
    auto cpB = [&](int s, int i0) {
        uint32_t Bs = smem + s*STAGE_BYTES + A_BYTES;
        #pragma unroll
        for (int p = 0; p < 6; ++p) {
            int idx = tid + p*256;            // < 1536
            int kk = idx >> 9;
            int ii = (idx >> 5) & 15;
            int c4 = idx & 31;
            cp16(Bs + (uint32_t)(((kk*16 + ii)*128 + c4*4)*4),
                 g_Wt + ((size_t)kk*ND + i0 + ii)*ND + o0 + c4*4);
        }
        asm volatile("cp.async.commit_group;" ::: "memory");
    };

    // ---- prologue: fill both stages (chunks 0,1) ----
    float4 vbuf[3];
    ldgA(0, vbuf);  stsA(0, vbuf);  cpB(0, 0);
    ldgA(16, vbuf); stsA(1, vbuf);  cpB(1, 16);

    for (int c = 0; c < 32; ++c) {
        const int s = c & 1;
        if (c < 30) asm volatile("cp.async.wait_group 1;" ::: "memory");
        else        asm volatile("cp.async.wait_group 0;" ::: "memory");
        __syncthreads();   // B(c) landed + A(c) STS visible + stage free

        if (c < 30) ldgA((c + 2) * 16, vbuf);   // prefetch next-next A into regs

        // ---- compute chunk c from stage s (same FFMA2 values/order as R5) ----
        const float* Asp = (const float*)(dsm + s*STAGE_BYTES);
        const float* Bsf = (const float*)(dsm + s*STAGE_BYTES + A_BYTES);
        #pragma unroll
        for (int ii = 0; ii < 16; ++ii) {
            const float4* ap = (const float4*)(Asp + ii*132 + ty*8);
            ull a[10];
            {
                float4 p0 = ap[0];
                a[0] = dupf(p0.x); a[1] = dupf(p0.y); a[2] = dupf(p0.z); a[3] = dupf(p0.w);
                float4 p1 = ap[1];
                a[4] = dupf(p1.x); a[5] = dupf(p1.y); a[6] = dupf(p1.z); a[7] = dupf(p1.w);
                float2 p2 = *(const float2*)(Asp + ii*132 + ty*8 + 8);
                a[8] = dupf(p2.x); a[9] = dupf(p2.y);
            }
            #pragma unroll
            for (int k = 0; k < 3; ++k) {
                const ulonglong2* bp = (const ulonglong2*)(Bsf + (k*16 + ii)*128 + tx*8);
                ulonglong2 b01 = bp[0];
                ulonglong2 b23 = bp[1];
                #pragma unroll
                for (int m = 0; m < 8; ++m) {
                    ffma2(acc[m][0], a[m+k], b01.x);
                    ffma2(acc[m][1], a[m+k], b01.y);
                    ffma2(acc[m][2], a[m+k], b23.x);
                    ffma2(acc[m][3], a[m+k], b23.y);
                }
            }
        }
        __syncthreads();   // compute on stage s done -> safe to refill

        if (c < 30) { stsA(s, vbuf); cpB(s, (c + 2) * 16); }
    }

    // ---- epilogue: +bias, relu, store to g_y ----
    float bias[8];
    #pragma unroll
    for (int j = 0; j < 8; ++j) bias[j] = cb[o0 + tx*8 + j];
    #pragma unroll
    for (int m = 0; m < 8; ++m) {
        int t = t0 + ty*8 + m;
        if (t < NT) {
            float outv[8];
            #pragma unroll
            for (int n = 0; n < 4; ++n) {
                float lo = __uint_as_float((unsigned)(acc[m][n] & 0xffffffffull));
                float hi = __uint_as_float((unsigned)(acc[m][n] >> 32));
                outv[2*n]   = fmaxf(lo + bias[2*n],   0.f);
                outv[2*n+1] = fmaxf(hi + bias[2*n+1], 0.f);
            }
            float4* yp = (float4*)(g_y + ((size_t)b*NT + t)*ND + o0 + tx*8);
            yp[0] = make_float4(outv[0], outv[1], outv[2], outv[3]);
            yp[1] = make_float4(outv[4], outv[5], outv[6], outv[7]);
        }
    }
}

// ---------------- K2: projections -> alphas_t[t<T], a2sum ----------------
__global__ void __launch_bounds__(256) k_proj(const float* __restrict__ mask,
        const float* __restrict__ w1, const float* __restrict__ b1,
        float* __restrict__ out_at) {
    int warp = threadIdx.x >> 5, lane = threadIdx.x & 31;
    int m = blockIdx.x * 8 + warp;
    if (m >= NB*NT) return;
    int b = m / NT, t = m - b*NT;
    const float4* yr  = (const float4*)(g_y + (size_t)m*ND);
    const float4* w1r = (const float4*)w1;
    float s[6] = {0.f,0.f,0.f,0.f,0.f,0.f};
    #pragma unroll
    for (int r = 0; r < 4; ++r) {
        int i4 = lane + 32*r;
        float4 h = yr[i4];
        float4 w = w1r[i4];
        s[0] += h.x*w.x + h.y*w.y + h.z*w.z + h.w*w.w;
        #pragma unroll
        for (int j = 0; j < 5; ++j) {
            float4 vv = *(const float4*)(g_v + j*ND + i4*4);
            s[1+j] += h.x*vv.x + h.y*vv.y + h.z*vv.z + h.w*vv.w;
        }
    }
    #pragma unroll
    for (int q = 0; q < 6; ++q)
        #pragma unroll
        for (int o = 16; o > 0; o >>= 1)
            s[q] += __shfl_xor_sync(0xffffffffu, s[q], o);
    if (lane == 0) {
        float mv = mask[b*NT + t];
        float alpha = fmaxf(sigmoidf_acc(s[0] + b1[0]), 0.f) * mv;
        float m2 = (t == 0) ? 1.f : mask[b*NT + t - 1];
        out_at[b*TT1 + t] = alpha + (m2 - mv) * 0.45f;
        float c2 = g_c2;
        float s2 = 0.f;
        #pragma unroll
        for (int j = 0; j < 5; ++j) s2 += fmaxf(sigmoidf_acc(s[1+j] + c2), 0.f);
        g_a2sum[m] = s2 * mv;
    }
}

// ---------------- K3: scalar CIF scan per batch ----------------
__global__ void k_scan(const float* __restrict__ mask, float* __restrict__ out) {
    int b = blockIdx.x, lane = threadIdx.x;
    float* out_at = out + OFF_AT;
    float* out_cp = out + OFF_CP;

    double s2 = 0.0;
    for (int t = lane; t < NT; t += 32) s2 += (double)g_a2sum[b*NT + t];
    #pragma unroll
    for (int o = 16; o > 0; o >>= 1) s2 += __shfl_xor_sync(0xffffffffu, s2, o);
    if (lane == 0) out[OFF_TN2 + b] = (float)s2;

    float tailv = mask[b*NT + NT - 1] * 0.45f;
    if (lane == 0) out_at[b*TT1 + NT] = tailv;

    float integ = 0.f; double asum = 0.0; int ntok = 0;
    for (int c = 0; c < TT1; c += 32) {
        int t = c + lane;
        float av = 0.f;
        if (t < NT) av = out_at[b*TT1 + t];
        else if (t == NT) av = tailv;
        float my_peak = 0.f, my_coeff = 0.f;
        int lim = TT1 - c; if (lim > 32) lim = 32;
        for (int s = 0; s < lim; ++s) {
            float alpha = __shfl_sync(0xffffffffu, av, s);
            asum += (double)alpha;
            float dist = 1.f - integ;
            integ += alpha;
            float fires = integ;
            float cur = alpha;
            if (fires >= 1.f) {
                integ -= 1.f;
                cur = dist;
                if (lane == 0) g_firepos[b*TT1 + ntok] = c + s;
                ntok++;
            }
            if (lane == s) { my_peak = fires; my_coeff = cur; }
        }
        if (t < TT1) { out_cp[b*TT1 + t] = my_peak; g_coeff[b*TT1 + t] = my_coeff; }
    }
    if (lane == 0) { out[OFF_TN + b] = floorf((float)asum); g_ntok[b] = ntok; }
}

// ---------------- K4: parallel token gather-sum ----------------
__global__ void __launch_bounds__(128) k_gather(const float* __restrict__ enc,
                                                float* __restrict__ out) {
    int b = blockIdx.y, n = blockIdx.x, tid = threadIdx.x;
    const float* at = out + OFF_AT;
    float4 acc = make_float4(0.f,0.f,0.f,0.f);
    if (n < g_ntok[b]) {
        int te = g_firepos[b*TT1 + n];
        int tstart = 0;
        if (n > 0) {
            int tp = g_firepos[b*TT1 + n - 1];
            float lw = at[b*TT1 + tp] - g_coeff[b*TT1 + tp];
            if (tp < NT) {
                float4 h = *(const float4*)(enc + ((size_t)b*NT + tp)*ND + tid*4);
                acc.x = lw*h.x; acc.y = lw*h.y; acc.z = lw*h.z; acc.w = lw*h.w;
            }
            tstart = tp + 1;
        }
        for (int t = tstart; t <= te; ++t) {
            if (t >= NT) break;
            float cf = g_coeff[b*TT1 + t];
            float4 h = *(const float4*)(enc + ((size_t)b*NT + t)*ND + tid*4);
            acc.x = fmaf(cf, h.x, acc.x);
            acc.y = fmaf(cf, h.y, acc.y);
            acc.z = fmaf(cf, h.z, acc.z);
            acc.w = fmaf(cf, h.w, acc.w);
        }
    }
    *(float4*)(out + ((size_t)(b*TT1 + n))*ND + tid*4) = acc;
}

// ---------------- launch ----------------
extern "C" void kernel_launch(void* const* d_in, const int* in_sizes, int n_in,
                              void* d_out, int out_size) {
    (void)in_sizes; (void)n_in; (void)out_size;
    const float* enc  = (const float*)d_in[0];
    const float* mask = (const float*)d_in[1];
    const float* cw   = (const float*)d_in[2];
    const float* cb   = (const float*)d_in[3];
    const float* uw   = (const float*)d_in[4];
    const float* ub   = (const float*)d_in[5];
    const float* w1   = (const float*)d_in[6];
    const float* b1   = (const float*)d_in[7];
    const float* w2   = (const float*)d_in[8];
    const float* b2   = (const float*)d_in[9];
    float* out = (float*)d_out;

    cudaFuncSetAttribute(k_conv_gemm, cudaFuncAttributeMaxDynamicSharedMemorySize, SMEM_CONV);

    k_prep_wt<<<(3*ND*ND + 255)/256, 256>>>(cw);
    k_prep_v<<<ND, 160>>>(uw, w2);
    k_prep_c2<<<1, 128>>>(ub, w2, b2);

    dim3 g1(8, 4, NB);               // t-tiles x o-tiles x batch
    k_conv_gemm<<<g1, 256, SMEM_CONV>>>(enc, cb);

    k_proj<<<(NB*NT)/8, 256>>>(mask, w1, b1, out + OFF_AT);
    k_scan<<<NB, 32>>>(mask, out);

    dim3 g4(TT1, NB);
    k_gather<<<g4, 128>>>(enc, out);
}